// round 12
// baseline (speedup 1.0000x reference)
#include <cuda_runtime.h>
#include <cuda_bf16.h>
#include <cstdint>
#include <math.h>

#define SEQ   512
#define BATCH 64
#define HID   1024
#define NG    4096                 // 4*HID
#define MROWS (SEQ * BATCH)        // 32768
#define STEP_CTAS 128

// ---- scratch (static device globals: allocation-free per harness rules) ----
__device__ float g_G[(size_t)MROWS * NG];        // 536 MB: G0 then reused for G1
__device__ float g_h0[(size_t)MROWS * HID];      // layer-0 h fp32 (only t=511 written)
__device__ float g_c[2 * BATCH * HID];           // final cell states
__device__ __nv_bfloat16 g_xhi[(size_t)MROWS * HID];
__device__ __nv_bfloat16 g_xlo[(size_t)MROWS * HID];
__device__ __nv_bfloat16 g_h0hi[(size_t)MROWS * HID];   // layer-0 h seq (bf16 split)
__device__ __nv_bfloat16 g_h0lo[(size_t)MROWS * HID];
__device__ __nv_bfloat16 g_h1hi[2 * BATCH * HID];       // layer-1 h ping-pong
__device__ __nv_bfloat16 g_h1lo[2 * BATCH * HID];
__device__ __nv_bfloat16 g_w0hiT[(size_t)NG * HID];     // Wih0^T [n][k]
__device__ __nv_bfloat16 g_w0loT[(size_t)NG * HID];
__device__ __nv_bfloat16 g_w1hiT[(size_t)NG * HID];     // Wih1^T [n][k]
__device__ __nv_bfloat16 g_w1loT[(size_t)NG * HID];
__device__ __nv_bfloat16 g_wh0hiT[(size_t)NG * HID];    // Whh0^T [n][k]
__device__ __nv_bfloat16 g_wh0loT[(size_t)NG * HID];
__device__ __nv_bfloat16 g_wh1hiT[(size_t)NG * HID];    // Whh1^T [n][k]
__device__ __nv_bfloat16 g_wh1loT[(size_t)NG * HID];

// ---- dataflow flags: g_flags[layer][cta] = number of steps completed ----
__device__ volatile int g_flags[2][STEP_CTAS];

// ---- software grid barrier (used ONCE per layer launch, for flag reset) ----
__device__ unsigned int g_bar_count = 0;
__device__ volatile unsigned int g_bar_gen = 0;

__device__ __forceinline__ void grid_barrier()
{
    __syncthreads();
    if (threadIdx.x == 0) {
        __threadfence();
        unsigned gen = g_bar_gen;                       // read BEFORE arriving
        unsigned arrived = atomicAdd(&g_bar_count, 1u);
        if (arrived == STEP_CTAS - 1) {
            g_bar_count = 0;
            __threadfence();
            g_bar_gen = gen + 1;
        } else {
            while (g_bar_gen == gen) { }
        }
    }
    __syncthreads();
}

// ============================================================================
// Conversion kernels
// ============================================================================
__global__ void split_kernel(const float* __restrict__ src,
                             __nv_bfloat16* __restrict__ hi,
                             __nv_bfloat16* __restrict__ lo, int n)
{
    int i = blockIdx.x * blockDim.x + threadIdx.x;
    if (i < n) {
        float v = src[i];
        __nv_bfloat16 h = __float2bfloat16(v);
        hi[i] = h;
        lo[i] = __float2bfloat16(v - __bfloat162float(h));
    }
}

// W [1024][4096] fp32  ->  WT hi/lo bf16 [4096][1024]
__global__ void transpose_split_kernel(const float* __restrict__ W,
                                       __nv_bfloat16* __restrict__ hiT,
                                       __nv_bfloat16* __restrict__ loT)
{
    __shared__ float tile[32][33];
    int tx = threadIdx.x, ty = threadIdx.y;
    int nb = blockIdx.x * 32;       // n base
    int kb = blockIdx.y * 32;       // k base
#pragma unroll
    for (int i = ty; i < 32; i += 8)
        tile[i][tx] = W[(size_t)(kb + i) * NG + nb + tx];
    __syncthreads();
#pragma unroll
    for (int i = ty; i < 32; i += 8) {
        float v = tile[tx][i];
        __nv_bfloat16 h = __float2bfloat16(v);
        size_t o = (size_t)(nb + i) * HID + kb + tx;
        hiT[o] = h;
        loT[o] = __float2bfloat16(v - __bfloat162float(h));
    }
}

// ============================================================================
// MMA / ldmatrix / cp.async primitives
// ============================================================================
__device__ __forceinline__ void cp16(uint32_t dst, const void* src)
{
    asm volatile("cp.async.cg.shared.global [%0], [%1], 16;"
                 :: "r"(dst), "l"(src) : "memory");
}
__device__ __forceinline__ void ldmx4(uint32_t* r, uint32_t addr)
{
    asm volatile("ldmatrix.sync.aligned.m8n8.x4.shared.b16 {%0,%1,%2,%3}, [%4];"
        : "=r"(r[0]), "=r"(r[1]), "=r"(r[2]), "=r"(r[3]) : "r"(addr));
}
__device__ __forceinline__ void mma_bf16(float* d, const uint32_t* a,
                                         uint32_t b0, uint32_t b1)
{
    asm volatile("mma.sync.aligned.m16n8k16.row.col.f32.bf16.bf16.f32 "
        "{%0,%1,%2,%3}, {%4,%5,%6,%7}, {%8,%9}, {%0,%1,%2,%3};"
        : "+f"(d[0]), "+f"(d[1]), "+f"(d[2]), "+f"(d[3])
        : "r"(a[0]), "r"(a[1]), "r"(a[2]), "r"(a[3]), "r"(b0), "r"(b1));
}

// ============================================================================
// Tensor-core big GEMM (split-bf16, 3 MMA): g_G = A @ W + b1 + b2
// (unchanged — verified, tensor pipe 48%)
// ============================================================================
#define GSTAGE 40960
#define AHOFF  0
#define ALOFF  10240
#define BHOFF  20480
#define BLOFF  30720

__device__ __forceinline__ void ld_stage_gemm(uint32_t base,
    const __nv_bfloat16* __restrict__ Ahi, const __nv_bfloat16* __restrict__ Alo,
    const __nv_bfloat16* __restrict__ BhiT, const __nv_bfloat16* __restrict__ BloT,
    int m0, int n0, int k0, int tid)
{
#pragma unroll
    for (int e = 0; e < 2; e++) {
        int g   = tid * 2 + e;
        int row = g >> 2;
        int seg = (g & 3) * 8;              // bf16 elems
        uint32_t doff = row * 80 + seg * 2; // bytes
        size_t soA = (size_t)(m0 + row) * HID + k0 + seg;
        size_t soB = (size_t)(n0 + row) * HID + k0 + seg;
        cp16(base + AHOFF + doff, Ahi  + soA);
        cp16(base + ALOFF + doff, Alo  + soA);
        cp16(base + BHOFF + doff, BhiT + soB);
        cp16(base + BLOFF + doff, BloT + soB);
    }
}

__global__ __launch_bounds__(256, 1) void gemm_mma_kernel(
    const __nv_bfloat16* __restrict__ Ahi, const __nv_bfloat16* __restrict__ Alo,
    const __nv_bfloat16* __restrict__ BhiT, const __nv_bfloat16* __restrict__ BloT,
    const float* __restrict__ b1, const float* __restrict__ b2)
{
    extern __shared__ char smem_dyn[];
    const uint32_t sb = (uint32_t)__cvta_generic_to_shared(smem_dyn);

    const int tid  = threadIdx.x;
    const int lane = tid & 31;
    const int wid  = tid >> 5;
    const int wm   = wid & 3;
    const int wn   = wid >> 2;
    const int m0   = blockIdx.y * 128;
    const int n0   = blockIdx.x * 128;

    float acc[2][8][4];
#pragma unroll
    for (int a = 0; a < 2; a++)
#pragma unroll
        for (int b = 0; b < 8; b++)
#pragma unroll
            for (int c = 0; c < 4; c++) acc[a][b][c] = 0.f;

    const int matq = lane >> 3;
    const int r8   = lane & 7;

    ld_stage_gemm(sb, Ahi, Alo, BhiT, BloT, m0, n0, 0, tid);
    asm volatile("cp.async.commit_group;");

#pragma unroll 1
    for (int c = 0; c < 32; c++) {
        if (c + 1 < 32) {
            ld_stage_gemm(sb + ((c + 1) & 1) * GSTAGE,
                          Ahi, Alo, BhiT, BloT, m0, n0, (c + 1) * 32, tid);
            asm volatile("cp.async.commit_group;");
            asm volatile("cp.async.wait_group 1;");
        } else {
            asm volatile("cp.async.wait_group 0;");
        }
        __syncthreads();
        const uint32_t st = sb + (c & 1) * GSTAGE;

#pragma unroll
        for (int kk = 0; kk < 32; kk += 16) {
            uint32_t ah[2][4], al[2][4];
#pragma unroll
            for (int mt = 0; mt < 2; mt++) {
                int rowA = wm * 32 + mt * 16 + (matq & 1) * 8 + r8;
                int colA = kk + (matq >> 1) * 8;
                uint32_t ad = st + rowA * 80 + colA * 2;
                ldmx4(ah[mt], ad + AHOFF);
                ldmx4(al[mt], ad + ALOFF);
            }
            uint32_t bh[4][4], bl[4][4];
#pragma unroll
            for (int ng = 0; ng < 4; ng++) {
                int rowB = wn * 64 + ng * 16 + (matq >> 1) * 8 + r8;
                int colB = kk + (matq & 1) * 8;
                uint32_t bd = st + rowB * 80 + colB * 2;
                ldmx4(bh[ng], bd + BHOFF);
                ldmx4(bl[ng], bd + BLOFF);
            }
#pragma unroll
            for (int mt = 0; mt < 2; mt++)
#pragma unroll
                for (int ng = 0; ng < 4; ng++)
#pragma unroll
                    for (int hf = 0; hf < 2; hf++) {
                        int nt = ng * 2 + hf;
                        mma_bf16(acc[mt][nt], ah[mt], bh[ng][hf * 2], bh[ng][hf * 2 + 1]);
                        mma_bf16(acc[mt][nt], ah[mt], bl[ng][hf * 2], bl[ng][hf * 2 + 1]);
                        mma_bf16(acc[mt][nt], al[mt], bh[ng][hf * 2], bh[ng][hf * 2 + 1]);
                    }
        }
        __syncthreads();
    }

#pragma unroll
    for (int mt = 0; mt < 2; mt++)
#pragma unroll
        for (int nt = 0; nt < 8; nt++) {
            int row = m0 + wm * 32 + mt * 16 + (lane >> 2);
            int col = n0 + wn * 64 + nt * 8 + (lane & 3) * 2;
            float bs0 = b1[col] + b2[col];
            float bs1 = b1[col + 1] + b2[col + 1];
            float2 v0 = make_float2(acc[mt][nt][0] + bs0, acc[mt][nt][1] + bs1);
            float2 v1 = make_float2(acc[mt][nt][2] + bs0, acc[mt][nt][3] + bs1);
            *(float2*)&g_G[(size_t)row * NG + col]       = v0;
            *(float2*)&g_G[(size_t)(row + 8) * NG + col] = v1;
        }
}

// ============================================================================
// Tensor-core persistent recurrence, dataflow-synchronized (NO per-step barrier).
// 128 CTAs x 256 thr. CTA owns 8 hidden cols -> 32 gate cols.
// Whh slice (hi/lo bf16) resident in SMEM all 512 steps.
// Sync: per-CTA monotonic flags; chunk c of h(t-1) is produced by CTAs
// c*16..c*16+15, and each thread's loads in a chunk hit exactly producer
// c*16 + (tid&15) -> inline single-flag poll per thread per chunk.
// G tile (8KB) prefetched into smem via cp.async at step start.
// SMEM map (bytes):
//   WHI 0..66048  WLO 66048..132096
//   H   132096..201728 (2 x [hi 17408 | lo 17408], row 272B)
//   SRED 201728..210176 (64 x 33 f32)   CST 210176..212224 (64 x 8 f32)
//   GS  212224..222464 (64 x 40 f32, row 160B)
// ============================================================================
#define R_WHI  0u
#define R_WLO  66048u
#define R_HB   132096u
#define R_HBUF 34816u
#define R_HLO  17408u
#define R_SRED 201728u
#define R_CST  210176u
#define R_GS   212224u
#define R_SMEM 222464

__global__ __launch_bounds__(256, 1) void lstm_layer_mma_kernel(
    const __nv_bfloat16* __restrict__ WhiT,   // Whh^T hi [4096][1024]
    const __nv_bfloat16* __restrict__ WloT,
    int layer, float* __restrict__ dout)
{
    extern __shared__ char smem_dyn[];
    const uint32_t sb = (uint32_t)__cvta_generic_to_shared(smem_dyn);
    float* sred = (float*)(smem_dyn + R_SRED);
    float* cst  = (float*)(smem_dyn + R_CST);
    float* gs   = (float*)(smem_dyn + R_GS);

    const int tid  = threadIdx.x;
    const int lane = tid & 31;
    const int wid  = tid >> 5;
    const int wm   = wid & 1;           // m half (32)
    const int wn   = (wid >> 1) & 1;    // n half (16 gate cols)
    const int kg   = wid >> 2;          // k group (64 of each 128-chunk)
    const int matq = lane >> 3;
    const int r8   = lane & 7;
    const int c0   = blockIdx.x * 8;    // hidden-col base
    const int seg16 = tid & 15;         // this thread's producer lane

    // reset own flag (replay safety) — globally ordered by the barrier below
    if (tid == 0) g_flags[layer][blockIdx.x] = 0;

    // ---- load Whh slice into smem (one time)
#pragma unroll 4
    for (int q = 0; q < 32; q++) {
        int id   = q * 256 + tid;       // 0..8191
        int half = id >> 12;            // 0 hi, 1 lo
        int idl  = id & 4095;
        int v    = idl >> 7;            // 0..31
        int seg  = idl & 127;           // 16B segment (8 bf16)
        const __nv_bfloat16* src = (half ? WloT : WhiT)
            + (size_t)((v >> 3) * HID + c0 + (v & 7)) * HID + seg * 8;
        cp16(sb + (half ? R_WLO : R_WHI) + v * 2064 + seg * 16, src);
    }
    asm volatile("cp.async.commit_group;");
    asm volatile("cp.async.wait_group 0;");

    grid_barrier();   // all flags reset + weights loaded before any step

    const __nv_bfloat16* hseqHi = (layer == 0) ? g_h0hi : g_h1hi;
    const __nv_bfloat16* hseqLo = (layer == 0) ? g_h0lo : g_h1lo;

#pragma unroll 1
    for (int t = 0; t < SEQ; t++) {
        // ---- prefetch G tile for this step into smem (2 cp16 per thread) ----
#pragma unroll
        for (int e = 0; e < 2; e++) {
            int id   = tid * 2 + e;       // 0..511
            int b    = id >> 3;
            int gate = (id >> 1) & 3;
            int half = id & 1;
            const float* src = g_G + (size_t)t * BATCH * NG
                               + (size_t)b * NG + gate * HID + c0 + half * 4;
            cp16(sb + R_GS + b * 160 + gate * 32 + half * 16, src);
        }
        asm volatile("cp.async.commit_group;");

        float acc[2][2][4];
#pragma unroll
        for (int a = 0; a < 2; a++)
#pragma unroll
            for (int b = 0; b < 2; b++)
#pragma unroll
                for (int c = 0; c < 4; c++) acc[a][b][c] = 0.f;

        if (t > 0) {
            const int rdIdx = (layer == 0) ? (t - 1) : ((t - 1) & 1);
            const __nv_bfloat16* hHi = hseqHi + (size_t)rdIdx * BATCH * HID;
            const __nv_bfloat16* hLo = hseqLo + (size_t)rdIdx * BATCH * HID;

            // chunk 0: poll producer, then load
            while (g_flags[layer][seg16] < t) { }
#pragma unroll
            for (int q = 0; q < 8; q++) {
                int id   = q * 256 + tid;
                int half = id >> 10;
                int idl  = id & 1023;
                int row  = idl >> 4;
                int seg  = idl & 15;
                const __nv_bfloat16* src = (half ? hLo : hHi)
                    + (size_t)row * HID + seg * 8;
                cp16(sb + R_HB + (half ? R_HLO : 0u) + row * 272 + seg * 16, src);
            }
            asm volatile("cp.async.commit_group;");

#pragma unroll 1
            for (int c = 0; c < 8; c++) {
                if (c < 7) {
                    while (g_flags[layer][(c + 1) * 16 + seg16] < t) { }
#pragma unroll
                    for (int q = 0; q < 8; q++) {
                        int id   = q * 256 + tid;
                        int half = id >> 10;
                        int idl  = id & 1023;
                        int row  = idl >> 4;
                        int seg  = idl & 15;
                        const __nv_bfloat16* src = (half ? hLo : hHi)
                            + (size_t)row * HID + (c + 1) * 128 + seg * 8;
                        cp16(sb + R_HB + ((c + 1) & 1) * R_HBUF
                             + (half ? R_HLO : 0u) + row * 272 + seg * 16, src);
                    }
                    asm volatile("cp.async.commit_group;");
                    asm volatile("cp.async.wait_group 1;");
                } else {
                    asm volatile("cp.async.wait_group 0;");
                }
                __syncthreads();

                const uint32_t hb = sb + R_HB + (c & 1) * R_HBUF;
#pragma unroll
                for (int kt = 0; kt < 4; kt++) {
                    const int klocal = kg * 64 + kt * 16;       // within chunk
                    const int kglob  = c * 128 + klocal;        // within K=1024
                    uint32_t ah[2][4], al[2][4];
#pragma unroll
                    for (int mt = 0; mt < 2; mt++) {
                        int rowA = wm * 32 + mt * 16 + (matq & 1) * 8 + r8;
                        int colA = klocal + (matq >> 1) * 8;
                        uint32_t ad = hb + rowA * 272 + colA * 2;
                        ldmx4(ah[mt], ad);
                        ldmx4(al[mt], ad + R_HLO);
                    }
                    uint32_t bh[4], bl[4];
                    {
                        int rowB = wn * 16 + (matq >> 1) * 8 + r8;
                        int colB = kglob + (matq & 1) * 8;
                        uint32_t bd = sb + R_WHI + rowB * 2064 + colB * 2;
                        ldmx4(bh, bd);
                        ldmx4(bl, bd + R_WLO);
                    }
#pragma unroll
                    for (int mt = 0; mt < 2; mt++)
#pragma unroll
                        for (int nt = 0; nt < 2; nt++) {
                            mma_bf16(acc[mt][nt], ah[mt], bh[nt * 2], bh[nt * 2 + 1]);
                            mma_bf16(acc[mt][nt], ah[mt], bl[nt * 2], bl[nt * 2 + 1]);
                            mma_bf16(acc[mt][nt], al[mt], bh[nt * 2], bh[nt * 2 + 1]);
                        }
                }
                __syncthreads();
            }

            // reduce the two k-groups into sred
            if (kg == 1) {
#pragma unroll
                for (int mt = 0; mt < 2; mt++)
#pragma unroll
                    for (int nt = 0; nt < 2; nt++) {
                        int r  = wm * 32 + mt * 16 + (lane >> 2);
                        int cc = wn * 16 + nt * 8 + (lane & 3) * 2;
                        sred[r * 33 + cc]           = acc[mt][nt][0];
                        sred[r * 33 + cc + 1]       = acc[mt][nt][1];
                        sred[(r + 8) * 33 + cc]     = acc[mt][nt][2];
                        sred[(r + 8) * 33 + cc + 1] = acc[mt][nt][3];
                    }
            }
            __syncthreads();
            if (kg == 0) {
#pragma unroll
                for (int mt = 0; mt < 2; mt++)
#pragma unroll
                    for (int nt = 0; nt < 2; nt++) {
                        int r  = wm * 32 + mt * 16 + (lane >> 2);
                        int cc = wn * 16 + nt * 8 + (lane & 3) * 2;
                        sred[r * 33 + cc]           += acc[mt][nt][0];
                        sred[r * 33 + cc + 1]       += acc[mt][nt][1];
                        sred[(r + 8) * 33 + cc]     += acc[mt][nt][2];
                        sred[(r + 8) * 33 + cc + 1] += acc[mt][nt][3];
                    }
            }
            __syncthreads();
        } else {
            asm volatile("cp.async.wait_group 0;");   // drain G prefetch
            __syncthreads();
        }

        // ---- fused cell update: 512 (b,j) pairs, 2 per thread ----
        const int wrIdx = (layer == 0) ? t : (t & 1);
        __nv_bfloat16* hdHi = ((layer == 0) ? g_h0hi : g_h1hi)
                              + (size_t)wrIdx * BATCH * HID;
        __nv_bfloat16* hdLo = ((layer == 0) ? g_h0lo : g_h1lo)
                              + (size_t)wrIdx * BATCH * HID;

#pragma unroll
        for (int p = tid; p < BATCH * 8; p += 256) {
            int b = p >> 3, j = p & 7;
            float ig = gs[b * 40 + 0 * 8 + j];
            float fg = gs[b * 40 + 1 * 8 + j];
            float og = gs[b * 40 + 2 * 8 + j];
            float gg = gs[b * 40 + 3 * 8 + j];
            if (t > 0) {
                ig += sred[b * 33 + j];
                fg += sred[b * 33 + 8 + j];
                og += sred[b * 33 + 16 + j];
                gg += sred[b * 33 + 24 + j];
            }
            float si = 1.f / (1.f + __expf(-ig));
            float sf = 1.f / (1.f + __expf(-fg));
            float so = 1.f / (1.f + __expf(-og));
            float tg = tanhf(gg);

            float cp = (t == 0) ? 0.f : cst[b * 8 + j];
            float cn = sf * cp + si * tg;
            float h  = so * tanhf(cn);
            cst[b * 8 + j] = cn;

            int hidx = b * HID + c0 + j;
            __nv_bfloat16 hh = __float2bfloat16(h);
            hdHi[hidx] = hh;
            hdLo[hidx] = __float2bfloat16(h - __bfloat162float(hh));

            if (layer == 1)
                dout[(size_t)(t * BATCH + b) * HID + c0 + j] = h;
            if (t == SEQ - 1) {
                g_c[layer * BATCH * HID + hidx] = cn;
                if (layer == 0)
                    g_h0[(size_t)(t * BATCH + b) * HID + c0 + j] = h;
            }
        }

        // publish h(t): all threads' stores done -> fence -> bump flag
        __syncthreads();
        if (tid == 0) {
            __threadfence();
            g_flags[layer][blockIdx.x] = t + 1;
        }
    }
}

// ============================================================================
// Copy h_n / c_n into the tail of d_out.
// Layout: [output 512*64*1024][h_n 2*64*1024][c_n 2*64*1024]
// ============================================================================
__global__ void finalize_kernel(float* __restrict__ dout)
{
    int i = blockIdx.x * blockDim.x + threadIdx.x;   // 0 .. 262143
    const size_t OUT_TAIL = (size_t)SEQ * BATCH * HID;
    int seg = i >> 16;          // 0: h_n0, 1: h_n1, 2: c_n0, 3: c_n1
    int off = i & 65535;
    float v;
    if (seg == 0)      v = g_h0[(size_t)(SEQ - 1) * BATCH * HID + off];
    else if (seg == 1) v = dout[(size_t)(SEQ - 1) * BATCH * HID + off];
    else if (seg == 2) v = g_c[off];
    else               v = g_c[BATCH * HID + off];
    dout[OUT_TAIL + (size_t)seg * 65536 + off] = v;
}

// ============================================================================
extern "C" void kernel_launch(void* const* d_in, const int* in_sizes, int n_in,
                              void* d_out, int out_size)
{
    const float* x    = (const float*)d_in[0];
    const float* Wih0 = (const float*)d_in[1];
    const float* bih0 = (const float*)d_in[2];
    const float* Whh0 = (const float*)d_in[3];
    const float* bhh0 = (const float*)d_in[4];
    const float* Wih1 = (const float*)d_in[5];
    const float* bih1 = (const float*)d_in[6];
    const float* Whh1 = (const float*)d_in[7];
    const float* bhh1 = (const float*)d_in[8];
    float* out = (float*)d_out;

    cudaFuncSetAttribute(gemm_mma_kernel,
                         cudaFuncAttributeMaxDynamicSharedMemorySize, 2 * GSTAGE);
    cudaFuncSetAttribute(lstm_layer_mma_kernel,
                         cudaFuncAttributeMaxDynamicSharedMemorySize, R_SMEM);

    __nv_bfloat16 *xhi, *xlo, *h0hi, *h0lo;
    __nv_bfloat16 *w0h, *w0l, *w1h, *w1l, *wh0h, *wh0l, *wh1h, *wh1l;
    cudaGetSymbolAddress((void**)&xhi,  g_xhi);
    cudaGetSymbolAddress((void**)&xlo,  g_xlo);
    cudaGetSymbolAddress((void**)&h0hi, g_h0hi);
    cudaGetSymbolAddress((void**)&h0lo, g_h0lo);
    cudaGetSymbolAddress((void**)&w0h,  g_w0hiT);
    cudaGetSymbolAddress((void**)&w0l,  g_w0loT);
    cudaGetSymbolAddress((void**)&w1h,  g_w1hiT);
    cudaGetSymbolAddress((void**)&w1l,  g_w1loT);
    cudaGetSymbolAddress((void**)&wh0h, g_wh0hiT);
    cudaGetSymbolAddress((void**)&wh0l, g_wh0loT);
    cudaGetSymbolAddress((void**)&wh1h, g_wh1hiT);
    cudaGetSymbolAddress((void**)&wh1l, g_wh1loT);

    const int NX = MROWS * HID;
    dim3 tg(NG / 32, HID / 32);          // transpose grid
    dim3 gg(NG / 128, MROWS / 128);      // gemm grid: 32 x 256

    // Phase 0: conversions
    split_kernel<<<NX / 256, 256>>>(x, xhi, xlo, NX);
    transpose_split_kernel<<<tg, dim3(32, 8)>>>(Wih0, w0h, w0l);
    transpose_split_kernel<<<tg, dim3(32, 8)>>>(Wih1, w1h, w1l);
    transpose_split_kernel<<<tg, dim3(32, 8)>>>(Whh0, wh0h, wh0l);
    transpose_split_kernel<<<tg, dim3(32, 8)>>>(Whh1, wh1h, wh1l);

    // Phase 1: G0 = x @ Wih0 + bih0 + bhh0   (tensor cores)
    gemm_mma_kernel<<<gg, 256, 2 * GSTAGE>>>(xhi, xlo, w0h, w0l, bih0, bhh0);

    // Phase 2: layer-0 recurrence (persistent, dataflow-synced)
    lstm_layer_mma_kernel<<<STEP_CTAS, 256, R_SMEM>>>(wh0h, wh0l, 0, out);

    // Phase 3: G1 = h0_seq @ Wih1 + bih1 + bhh1   (tensor cores)
    gemm_mma_kernel<<<gg, 256, 2 * GSTAGE>>>(h0hi, h0lo, w1h, w1l, bih1, bhh1);

    // Phase 4: layer-1 recurrence (directly into d_out)
    lstm_layer_mma_kernel<<<STEP_CTAS, 256, R_SMEM>>>(wh1h, wh1l, 1, out);

    // Phase 5: h_n / c_n
    finalize_kernel<<<1024, 256>>>(out);
}

// round 13
// speedup vs baseline: 1.1675x; 1.1675x over previous
#include <cuda_runtime.h>
#include <cuda_bf16.h>
#include <cstdint>
#include <math.h>

#define SEQ   512
#define BATCH 64
#define HID   1024
#define NG    4096                 // 4*HID
#define MROWS (SEQ * BATCH)        // 32768
#define STEP_CTAS 128

// ---- scratch (static device globals: allocation-free per harness rules) ----
__device__ float g_G[(size_t)MROWS * NG];        // 536 MB: G0 then reused for G1
__device__ float g_h0[(size_t)MROWS * HID];      // layer-0 h fp32 (only t=511 written)
__device__ float g_c[2 * BATCH * HID];           // final cell states
__device__ __nv_bfloat16 g_xhi[(size_t)MROWS * HID];
__device__ __nv_bfloat16 g_xlo[(size_t)MROWS * HID];
__device__ __nv_bfloat16 g_h0hi[(size_t)MROWS * HID];   // layer-0 h seq (bf16 split)
__device__ __nv_bfloat16 g_h0lo[(size_t)MROWS * HID];
__device__ __nv_bfloat16 g_h1hi[2 * BATCH * HID];       // layer-1 h ping-pong
__device__ __nv_bfloat16 g_h1lo[2 * BATCH * HID];
__device__ __nv_bfloat16 g_w0hiT[(size_t)NG * HID];     // Wih0^T [n][k]
__device__ __nv_bfloat16 g_w0loT[(size_t)NG * HID];
__device__ __nv_bfloat16 g_w1hiT[(size_t)NG * HID];     // Wih1^T [n][k]
__device__ __nv_bfloat16 g_w1loT[(size_t)NG * HID];
__device__ __nv_bfloat16 g_wh0hiT[(size_t)NG * HID];    // Whh0^T [n][k]
__device__ __nv_bfloat16 g_wh0loT[(size_t)NG * HID];
__device__ __nv_bfloat16 g_wh1hiT[(size_t)NG * HID];    // Whh1^T [n][k]
__device__ __nv_bfloat16 g_wh1loT[(size_t)NG * HID];

// ---- fast distributed barrier state (per layer, monotonic within launch) ----
__device__ volatile int g_arrive[2][STEP_CTAS];
__device__ volatile int g_release[2];

// ---- classic atomic grid barrier (used ONCE per layer launch, for reset) ----
__device__ unsigned int g_bar_count = 0;
__device__ volatile unsigned int g_bar_gen = 0;

__device__ __forceinline__ void grid_barrier()
{
    __syncthreads();
    if (threadIdx.x == 0) {
        __threadfence();
        unsigned gen = g_bar_gen;                       // read BEFORE arriving
        unsigned arrived = atomicAdd(&g_bar_count, 1u);
        if (arrived == STEP_CTAS - 1) {
            g_bar_count = 0;
            __threadfence();
            g_bar_gen = gen + 1;
        } else {
            while (g_bar_gen == gen) { }
        }
    }
    __syncthreads();
}

// Fast lockstep barrier: distributed arrivals + CTA0 gather + release word.
// gen must be monotonically increasing (use t+1).
__device__ __forceinline__ void fast_barrier(int layer, int gen)
{
    __syncthreads();
    if (threadIdx.x == 0) {
        __threadfence();
        g_arrive[layer][blockIdx.x] = gen;
    }
    if (blockIdx.x == 0) {
        if (threadIdx.x < STEP_CTAS)
            while (g_arrive[layer][threadIdx.x] < gen) { }
        __syncthreads();
        if (threadIdx.x == 0) {
            __threadfence();
            g_release[layer] = gen;
        }
    }
    if (threadIdx.x == 0)
        while (g_release[layer] < gen) { }
    __syncthreads();
}

// ============================================================================
// Conversion kernels
// ============================================================================
__global__ void split_kernel(const float* __restrict__ src,
                             __nv_bfloat16* __restrict__ hi,
                             __nv_bfloat16* __restrict__ lo, int n)
{
    int i = blockIdx.x * blockDim.x + threadIdx.x;
    if (i < n) {
        float v = src[i];
        __nv_bfloat16 h = __float2bfloat16(v);
        hi[i] = h;
        lo[i] = __float2bfloat16(v - __bfloat162float(h));
    }
}

// W [1024][4096] fp32  ->  WT hi/lo bf16 [4096][1024]
__global__ void transpose_split_kernel(const float* __restrict__ W,
                                       __nv_bfloat16* __restrict__ hiT,
                                       __nv_bfloat16* __restrict__ loT)
{
    __shared__ float tile[32][33];
    int tx = threadIdx.x, ty = threadIdx.y;
    int nb = blockIdx.x * 32;       // n base
    int kb = blockIdx.y * 32;       // k base
#pragma unroll
    for (int i = ty; i < 32; i += 8)
        tile[i][tx] = W[(size_t)(kb + i) * NG + nb + tx];
    __syncthreads();
#pragma unroll
    for (int i = ty; i < 32; i += 8) {
        float v = tile[tx][i];
        __nv_bfloat16 h = __float2bfloat16(v);
        size_t o = (size_t)(nb + i) * HID + kb + tx;
        hiT[o] = h;
        loT[o] = __float2bfloat16(v - __bfloat162float(h));
    }
}

// ============================================================================
// MMA / ldmatrix / cp.async primitives
// ============================================================================
__device__ __forceinline__ void cp16(uint32_t dst, const void* src)
{
    asm volatile("cp.async.cg.shared.global [%0], [%1], 16;"
                 :: "r"(dst), "l"(src) : "memory");
}
__device__ __forceinline__ void ldmx4(uint32_t* r, uint32_t addr)
{
    asm volatile("ldmatrix.sync.aligned.m8n8.x4.shared.b16 {%0,%1,%2,%3}, [%4];"
        : "=r"(r[0]), "=r"(r[1]), "=r"(r[2]), "=r"(r[3]) : "r"(addr));
}
__device__ __forceinline__ void mma_bf16(float* d, const uint32_t* a,
                                         uint32_t b0, uint32_t b1)
{
    asm volatile("mma.sync.aligned.m16n8k16.row.col.f32.bf16.bf16.f32 "
        "{%0,%1,%2,%3}, {%4,%5,%6,%7}, {%8,%9}, {%0,%1,%2,%3};"
        : "+f"(d[0]), "+f"(d[1]), "+f"(d[2]), "+f"(d[3])
        : "r"(a[0]), "r"(a[1]), "r"(a[2]), "r"(a[3]), "r"(b0), "r"(b1));
}

// ============================================================================
// Tensor-core big GEMM (split-bf16, 3 MMA): g_G = A @ W + b1 + b2
// CTA tile 128x128, BK=32, 8 warps, 3-stage cp.async pipeline (123KB smem).
// ============================================================================
#define GSTAGE 40960
#define AHOFF  0
#define ALOFF  10240
#define BHOFF  20480
#define BLOFF  30720

__device__ __forceinline__ void ld_stage_gemm(uint32_t base,
    const __nv_bfloat16* __restrict__ Ahi, const __nv_bfloat16* __restrict__ Alo,
    const __nv_bfloat16* __restrict__ BhiT, const __nv_bfloat16* __restrict__ BloT,
    int m0, int n0, int k0, int tid)
{
#pragma unroll
    for (int e = 0; e < 2; e++) {
        int g   = tid * 2 + e;
        int row = g >> 2;
        int seg = (g & 3) * 8;              // bf16 elems
        uint32_t doff = row * 80 + seg * 2; // bytes
        size_t soA = (size_t)(m0 + row) * HID + k0 + seg;
        size_t soB = (size_t)(n0 + row) * HID + k0 + seg;
        cp16(base + AHOFF + doff, Ahi  + soA);
        cp16(base + ALOFF + doff, Alo  + soA);
        cp16(base + BHOFF + doff, BhiT + soB);
        cp16(base + BLOFF + doff, BloT + soB);
    }
}

__global__ __launch_bounds__(256, 1) void gemm_mma_kernel(
    const __nv_bfloat16* __restrict__ Ahi, const __nv_bfloat16* __restrict__ Alo,
    const __nv_bfloat16* __restrict__ BhiT, const __nv_bfloat16* __restrict__ BloT,
    const float* __restrict__ b1, const float* __restrict__ b2)
{
    extern __shared__ char smem_dyn[];
    const uint32_t sb = (uint32_t)__cvta_generic_to_shared(smem_dyn);

    const int tid  = threadIdx.x;
    const int lane = tid & 31;
    const int wid  = tid >> 5;
    const int wm   = wid & 3;
    const int wn   = wid >> 2;
    const int m0   = blockIdx.y * 128;
    const int n0   = blockIdx.x * 128;

    float acc[2][8][4];
#pragma unroll
    for (int a = 0; a < 2; a++)
#pragma unroll
        for (int b = 0; b < 8; b++)
#pragma unroll
            for (int c = 0; c < 4; c++) acc[a][b][c] = 0.f;

    const int matq = lane >> 3;
    const int r8   = lane & 7;

    ld_stage_gemm(sb,          Ahi, Alo, BhiT, BloT, m0, n0, 0,  tid);
    asm volatile("cp.async.commit_group;");
    ld_stage_gemm(sb + GSTAGE, Ahi, Alo, BhiT, BloT, m0, n0, 32, tid);
    asm volatile("cp.async.commit_group;");

    int buf = 0;
#pragma unroll 1
    for (int c = 0; c < 32; c++) {
        if (c + 2 < 32) {
            int nb = (buf + 2) % 3;
            ld_stage_gemm(sb + nb * GSTAGE,
                          Ahi, Alo, BhiT, BloT, m0, n0, (c + 2) * 32, tid);
            asm volatile("cp.async.commit_group;");
            asm volatile("cp.async.wait_group 2;");
        } else if (c + 1 < 32) {
            asm volatile("cp.async.wait_group 1;");
        } else {
            asm volatile("cp.async.wait_group 0;");
        }
        __syncthreads();
        const uint32_t st = sb + buf * GSTAGE;

#pragma unroll
        for (int kk = 0; kk < 32; kk += 16) {
            uint32_t ah[2][4], al[2][4];
#pragma unroll
            for (int mt = 0; mt < 2; mt++) {
                int rowA = wm * 32 + mt * 16 + (matq & 1) * 8 + r8;
                int colA = kk + (matq >> 1) * 8;
                uint32_t ad = st + rowA * 80 + colA * 2;
                ldmx4(ah[mt], ad + AHOFF);
                ldmx4(al[mt], ad + ALOFF);
            }
            uint32_t bh[4][4], bl[4][4];
#pragma unroll
            for (int ng = 0; ng < 4; ng++) {
                int rowB = wn * 64 + ng * 16 + (matq >> 1) * 8 + r8;
                int colB = kk + (matq & 1) * 8;
                uint32_t bd = st + rowB * 80 + colB * 2;
                ldmx4(bh[ng], bd + BHOFF);
                ldmx4(bl[ng], bd + BLOFF);
            }
#pragma unroll
            for (int mt = 0; mt < 2; mt++)
#pragma unroll
                for (int ng = 0; ng < 4; ng++)
#pragma unroll
                    for (int hf = 0; hf < 2; hf++) {
                        int nt = ng * 2 + hf;
                        mma_bf16(acc[mt][nt], ah[mt], bh[ng][hf * 2], bh[ng][hf * 2 + 1]);
                        mma_bf16(acc[mt][nt], ah[mt], bl[ng][hf * 2], bl[ng][hf * 2 + 1]);
                        mma_bf16(acc[mt][nt], al[mt], bh[ng][hf * 2], bh[ng][hf * 2 + 1]);
                    }
        }
        __syncthreads();
        buf = (buf + 1) % 3;
    }

#pragma unroll
    for (int mt = 0; mt < 2; mt++)
#pragma unroll
        for (int nt = 0; nt < 8; nt++) {
            int row = m0 + wm * 32 + mt * 16 + (lane >> 2);
            int col = n0 + wn * 64 + nt * 8 + (lane & 3) * 2;
            float bs0 = b1[col] + b2[col];
            float bs1 = b1[col + 1] + b2[col + 1];
            float2 v0 = make_float2(acc[mt][nt][0] + bs0, acc[mt][nt][1] + bs1);
            float2 v1 = make_float2(acc[mt][nt][2] + bs0, acc[mt][nt][3] + bs1);
            *(float2*)&g_G[(size_t)row * NG + col]       = v0;
            *(float2*)&g_G[(size_t)(row + 8) * NG + col] = v1;
        }
}

// ============================================================================
// Tensor-core persistent recurrence, lockstep with FAST distributed barrier.
// 128 CTAs x 256 thr. CTA owns 8 hidden cols -> 32 gate cols.
// Whh slice (hi/lo bf16) resident in SMEM all 512 steps.
// G tile (8KB) prefetched into smem via cp.async at step start.
// SMEM map (bytes):
//   WHI 0..66048  WLO 66048..132096
//   H   132096..201728 (2 x [hi 17408 | lo 17408], row 272B)
//   SRED 201728..210176 (64 x 33 f32)   CST 210176..212224 (64 x 8 f32)
//   GS  212224..222464 (64 x 40 f32, row 160B)
// ============================================================================
#define R_WHI  0u
#define R_WLO  66048u
#define R_HB   132096u
#define R_HBUF 34816u
#define R_HLO  17408u
#define R_SRED 201728u
#define R_CST  210176u
#define R_GS   212224u
#define R_SMEM 222464

__global__ __launch_bounds__(256, 1) void lstm_layer_mma_kernel(
    const __nv_bfloat16* __restrict__ WhiT,   // Whh^T hi [4096][1024]
    const __nv_bfloat16* __restrict__ WloT,
    int layer, float* __restrict__ dout)
{
    extern __shared__ char smem_dyn[];
    const uint32_t sb = (uint32_t)__cvta_generic_to_shared(smem_dyn);
    float* sred = (float*)(smem_dyn + R_SRED);
    float* cst  = (float*)(smem_dyn + R_CST);
    float* gs   = (float*)(smem_dyn + R_GS);

    const int tid  = threadIdx.x;
    const int lane = tid & 31;
    const int wid  = tid >> 5;
    const int wm   = wid & 1;           // m half (32)
    const int wn   = (wid >> 1) & 1;    // n half (16 gate cols)
    const int kg   = wid >> 2;          // k group (64 of each 128-chunk)
    const int matq = lane >> 3;
    const int r8   = lane & 7;
    const int c0   = blockIdx.x * 8;    // hidden-col base

    // reset fast-barrier state (replay safety), ordered by grid_barrier below
    if (tid == 0) {
        g_arrive[layer][blockIdx.x] = 0;
        if (blockIdx.x == 0) g_release[layer] = 0;
    }

    // ---- load Whh slice into smem (one time)
#pragma unroll 4
    for (int q = 0; q < 32; q++) {
        int id   = q * 256 + tid;       // 0..8191
        int half = id >> 12;            // 0 hi, 1 lo
        int idl  = id & 4095;
        int v    = idl >> 7;            // 0..31
        int seg  = idl & 127;           // 16B segment (8 bf16)
        const __nv_bfloat16* src = (half ? WloT : WhiT)
            + (size_t)((v >> 3) * HID + c0 + (v & 7)) * HID + seg * 8;
        cp16(sb + (half ? R_WLO : R_WHI) + v * 2064 + seg * 16, src);
    }
    asm volatile("cp.async.commit_group;");
    asm volatile("cp.async.wait_group 0;");

    grid_barrier();   // barrier state reset + weights loaded before any step

    const __nv_bfloat16* hseqHi = (layer == 0) ? g_h0hi : g_h1hi;
    const __nv_bfloat16* hseqLo = (layer == 0) ? g_h0lo : g_h1lo;

#pragma unroll 1
    for (int t = 0; t < SEQ; t++) {
        // ---- prefetch G tile for this step into smem (2 cp16 per thread) ----
#pragma unroll
        for (int e = 0; e < 2; e++) {
            int id   = tid * 2 + e;       // 0..511
            int b    = id >> 3;
            int gate = (id >> 1) & 3;
            int half = id & 1;
            const float* src = g_G + (size_t)t * BATCH * NG
                               + (size_t)b * NG + gate * HID + c0 + half * 4;
            cp16(sb + R_GS + b * 160 + gate * 32 + half * 16, src);
        }
        asm volatile("cp.async.commit_group;");

        float acc[2][2][4];
#pragma unroll
        for (int a = 0; a < 2; a++)
#pragma unroll
            for (int b = 0; b < 2; b++)
#pragma unroll
                for (int c = 0; c < 4; c++) acc[a][b][c] = 0.f;

        if (t > 0) {
            const int rdIdx = (layer == 0) ? (t - 1) : ((t - 1) & 1);
            const __nv_bfloat16* hHi = hseqHi + (size_t)rdIdx * BATCH * HID;
            const __nv_bfloat16* hLo = hseqLo + (size_t)rdIdx * BATCH * HID;

            // preload chunk 0 into buf 0
#pragma unroll
            for (int q = 0; q < 8; q++) {
                int id   = q * 256 + tid;
                int half = id >> 10;
                int idl  = id & 1023;
                int row  = idl >> 4;
                int seg  = idl & 15;
                const __nv_bfloat16* src = (half ? hLo : hHi)
                    + (size_t)row * HID + seg * 8;
                cp16(sb + R_HB + (half ? R_HLO : 0u) + row * 272 + seg * 16, src);
            }
            asm volatile("cp.async.commit_group;");

#pragma unroll 1
            for (int c = 0; c < 8; c++) {
                if (c < 7) {
#pragma unroll
                    for (int q = 0; q < 8; q++) {
                        int id   = q * 256 + tid;
                        int half = id >> 10;
                        int idl  = id & 1023;
                        int row  = idl >> 4;
                        int seg  = idl & 15;
                        const __nv_bfloat16* src = (half ? hLo : hHi)
                            + (size_t)row * HID + (c + 1) * 128 + seg * 8;
                        cp16(sb + R_HB + ((c + 1) & 1) * R_HBUF
                             + (half ? R_HLO : 0u) + row * 272 + seg * 16, src);
                    }
                    asm volatile("cp.async.commit_group;");
                    asm volatile("cp.async.wait_group 1;");
                } else {
                    asm volatile("cp.async.wait_group 0;");
                }
                __syncthreads();

                const uint32_t hb = sb + R_HB + (c & 1) * R_HBUF;
#pragma unroll
                for (int kt = 0; kt < 4; kt++) {
                    const int klocal = kg * 64 + kt * 16;       // within chunk
                    const int kglob  = c * 128 + klocal;        // within K=1024
                    uint32_t ah[2][4], al[2][4];
#pragma unroll
                    for (int mt = 0; mt < 2; mt++) {
                        int rowA = wm * 32 + mt * 16 + (matq & 1) * 8 + r8;
                        int colA = klocal + (matq >> 1) * 8;
                        uint32_t ad = hb + rowA * 272 + colA * 2;
                        ldmx4(ah[mt], ad);
                        ldmx4(al[mt], ad + R_HLO);
                    }
                    uint32_t bh[4], bl[4];
                    {
                        int rowB = wn * 16 + (matq >> 1) * 8 + r8;
                        int colB = kglob + (matq & 1) * 8;
                        uint32_t bd = sb + R_WHI + rowB * 2064 + colB * 2;
                        ldmx4(bh, bd);
                        ldmx4(bl, bd + R_WLO);
                    }
#pragma unroll
                    for (int mt = 0; mt < 2; mt++)
#pragma unroll
                        for (int nt = 0; nt < 2; nt++) {
                            mma_bf16(acc[mt][nt], ah[mt], bh[nt * 2], bh[nt * 2 + 1]);
                            mma_bf16(acc[mt][nt], ah[mt], bl[nt * 2], bl[nt * 2 + 1]);
                            mma_bf16(acc[mt][nt], al[mt], bh[nt * 2], bh[nt * 2 + 1]);
                        }
                }
                __syncthreads();
            }

            // reduce the two k-groups into sred
            if (kg == 1) {
#pragma unroll
                for (int mt = 0; mt < 2; mt++)
#pragma unroll
                    for (int nt = 0; nt < 2; nt++) {
                        int r  = wm * 32 + mt * 16 + (lane >> 2);
                        int cc = wn * 16 + nt * 8 + (lane & 3) * 2;
                        sred[r * 33 + cc]           = acc[mt][nt][0];
                        sred[r * 33 + cc + 1]       = acc[mt][nt][1];
                        sred[(r + 8) * 33 + cc]     = acc[mt][nt][2];
                        sred[(r + 8) * 33 + cc + 1] = acc[mt][nt][3];
                    }
            }
            __syncthreads();
            if (kg == 0) {
#pragma unroll
                for (int mt = 0; mt < 2; mt++)
#pragma unroll
                    for (int nt = 0; nt < 2; nt++) {
                        int r  = wm * 32 + mt * 16 + (lane >> 2);
                        int cc = wn * 16 + nt * 8 + (lane & 3) * 2;
                        sred[r * 33 + cc]           += acc[mt][nt][0];
                        sred[r * 33 + cc + 1]       += acc[mt][nt][1];
                        sred[(r + 8) * 33 + cc]     += acc[mt][nt][2];
                        sred[(r + 8) * 33 + cc + 1] += acc[mt][nt][3];
                    }
            }
            __syncthreads();
        } else {
            asm volatile("cp.async.wait_group 0;");   // drain G prefetch
            __syncthreads();
        }

        // ---- fused cell update: 512 (b,j) pairs, 2 per thread ----
        const int wrIdx = (layer == 0) ? t : (t & 1);
        __nv_bfloat16* hdHi = ((layer == 0) ? g_h0hi : g_h1hi)
                              + (size_t)wrIdx * BATCH * HID;
        __nv_bfloat16* hdLo = ((layer == 0) ? g_h0lo : g_h1lo)
                              + (size_t)wrIdx * BATCH * HID;

#pragma unroll
        for (int p = tid; p < BATCH * 8; p += 256) {
            int b = p >> 3, j = p & 7;
            float ig = gs[b * 40 + 0 * 8 + j];
            float fg = gs[b * 40 + 1 * 8 + j];
            float og = gs[b * 40 + 2 * 8 + j];
            float gg = gs[b * 40 + 3 * 8 + j];
            if (t > 0) {
                ig += sred[b * 33 + j];
                fg += sred[b * 33 + 8 + j];
                og += sred[b * 33 + 16 + j];
                gg += sred[b * 33 + 24 + j];
            }
            float si = 1.f / (1.f + __expf(-ig));
            float sf = 1.f / (1.f + __expf(-fg));
            float so = 1.f / (1.f + __expf(-og));
            float tg = tanhf(gg);

            float cp = (t == 0) ? 0.f : cst[b * 8 + j];
            float cn = sf * cp + si * tg;
            float h  = so * tanhf(cn);
            cst[b * 8 + j] = cn;

            int hidx = b * HID + c0 + j;
            __nv_bfloat16 hh = __float2bfloat16(h);
            hdHi[hidx] = hh;
            hdLo[hidx] = __float2bfloat16(h - __bfloat162float(hh));

            if (layer == 1)
                dout[(size_t)(t * BATCH + b) * HID + c0 + j] = h;
            if (t == SEQ - 1) {
                g_c[layer * BATCH * HID + hidx] = cn;
                if (layer == 0)
                    g_h0[(size_t)(t * BATCH + b) * HID + c0 + j] = h;
            }
        }

        fast_barrier(layer, t + 1);   // h(t) globally visible before step t+1
    }
}

// ============================================================================
// Copy h_n / c_n into the tail of d_out.
// Layout: [output 512*64*1024][h_n 2*64*1024][c_n 2*64*1024]
// ============================================================================
__global__ void finalize_kernel(float* __restrict__ dout)
{
    int i = blockIdx.x * blockDim.x + threadIdx.x;   // 0 .. 262143
    const size_t OUT_TAIL = (size_t)SEQ * BATCH * HID;
    int seg = i >> 16;          // 0: h_n0, 1: h_n1, 2: c_n0, 3: c_n1
    int off = i & 65535;
    float v;
    if (seg == 0)      v = g_h0[(size_t)(SEQ - 1) * BATCH * HID + off];
    else if (seg == 1) v = dout[(size_t)(SEQ - 1) * BATCH * HID + off];
    else if (seg == 2) v = g_c[off];
    else               v = g_c[BATCH * HID + off];
    dout[OUT_TAIL + (size_t)seg * 65536 + off] = v;
}

// ============================================================================
extern "C" void kernel_launch(void* const* d_in, const int* in_sizes, int n_in,
                              void* d_out, int out_size)
{
    const float* x    = (const float*)d_in[0];
    const float* Wih0 = (const float*)d_in[1];
    const float* bih0 = (const float*)d_in[2];
    const float* Whh0 = (const float*)d_in[3];
    const float* bhh0 = (const float*)d_in[4];
    const float* Wih1 = (const float*)d_in[5];
    const float* bih1 = (const float*)d_in[6];
    const float* Whh1 = (const float*)d_in[7];
    const float* bhh1 = (const float*)d_in[8];
    float* out = (float*)d_out;

    cudaFuncSetAttribute(gemm_mma_kernel,
                         cudaFuncAttributeMaxDynamicSharedMemorySize, 3 * GSTAGE);
    cudaFuncSetAttribute(lstm_layer_mma_kernel,
                         cudaFuncAttributeMaxDynamicSharedMemorySize, R_SMEM);

    __nv_bfloat16 *xhi, *xlo, *h0hi, *h0lo;
    __nv_bfloat16 *w0h, *w0l, *w1h, *w1l, *wh0h, *wh0l, *wh1h, *wh1l;
    cudaGetSymbolAddress((void**)&xhi,  g_xhi);
    cudaGetSymbolAddress((void**)&xlo,  g_xlo);
    cudaGetSymbolAddress((void**)&h0hi, g_h0hi);
    cudaGetSymbolAddress((void**)&h0lo, g_h0lo);
    cudaGetSymbolAddress((void**)&w0h,  g_w0hiT);
    cudaGetSymbolAddress((void**)&w0l,  g_w0loT);
    cudaGetSymbolAddress((void**)&w1h,  g_w1hiT);
    cudaGetSymbolAddress((void**)&w1l,  g_w1loT);
    cudaGetSymbolAddress((void**)&wh0h, g_wh0hiT);
    cudaGetSymbolAddress((void**)&wh0l, g_wh0loT);
    cudaGetSymbolAddress((void**)&wh1h, g_wh1hiT);
    cudaGetSymbolAddress((void**)&wh1l, g_wh1loT);

    const int NX = MROWS * HID;
    dim3 tg(NG / 32, HID / 32);          // transpose grid
    dim3 gg(NG / 128, MROWS / 128);      // gemm grid: 32 x 256

    // Phase 0: conversions
    split_kernel<<<NX / 256, 256>>>(x, xhi, xlo, NX);
    transpose_split_kernel<<<tg, dim3(32, 8)>>>(Wih0, w0h, w0l);
    transpose_split_kernel<<<tg, dim3(32, 8)>>>(Wih1, w1h, w1l);
    transpose_split_kernel<<<tg, dim3(32, 8)>>>(Whh0, wh0h, wh0l);
    transpose_split_kernel<<<tg, dim3(32, 8)>>>(Whh1, wh1h, wh1l);

    // Phase 1: G0 = x @ Wih0 + bih0 + bhh0   (tensor cores)
    gemm_mma_kernel<<<gg, 256, 3 * GSTAGE>>>(xhi, xlo, w0h, w0l, bih0, bhh0);

    // Phase 2: layer-0 recurrence (persistent, fast lockstep barrier)
    lstm_layer_mma_kernel<<<STEP_CTAS, 256, R_SMEM>>>(wh0h, wh0l, 0, out);

    // Phase 3: G1 = h0_seq @ Wih1 + bih1 + bhh1   (tensor cores)
    gemm_mma_kernel<<<gg, 256, 3 * GSTAGE>>>(h0hi, h0lo, w1h, w1l, bih1, bhh1);

    // Phase 4: layer-1 recurrence (directly into d_out)
    lstm_layer_mma_kernel<<<STEP_CTAS, 256, R_SMEM>>>(wh1h, wh1l, 1, out);

    // Phase 5: h_n / c_n
    finalize_kernel<<<1024, 256>>>(out);
}